// round 10
// baseline (speedup 1.0000x reference)
#include <cuda_runtime.h>
#include <cstdint>
#include <stdint.h>
#include <math.h>

#define F_N   65536
#define LPL   8
#define NLNK  8192
#define DGD   64
#define DD    32
#define NITER 8

typedef unsigned long long ull;

// ---------------- device scratch (no allocations allowed) ----------------
__device__ float g_path[F_N * DD];            // 8 MB   path_state
__device__ float g_link[NLNK * DD];           // 1 MB   link_state
__device__ float g_mlx [NLNK * 96];           // 3 MB   link_state @ pg_w + b0
__device__ float g_pss [(size_t)F_N * 9 * DD];// 75.5MB [F,9,32]
// packed (pair-along-j) weights, computed once per run by k_pack
__device__ ull g_u2z[16*32], g_u2r[16*32], g_u2h[16*32];  // path GRU U
__device__ ull g_w2[16*96], g_u2[16*96], g_p2[16*96];     // link GRU W/U + pg_w
__device__ ull g_aw2[16*32];                              // att_w

// ---------------- math helpers ----------------
__device__ __forceinline__ float seluf(float x) {
    const float sc = 1.0507009873554804934f;
    const float al = 1.6732632423543772848f;
    return x > 0.f ? sc * x : sc * al * expm1f(x);
}
__device__ __forceinline__ float sigmoidf(float x) {
    return __fdividef(1.0f, 1.0f + __expf(-x));
}
__device__ __forceinline__ float fast_tanh(float x) {
    float e = __expf(2.0f * x);
    return 1.0f - __fdividef(2.0f, e + 1.0f);
}
__device__ __forceinline__ ull pack2(float lo, float hi) {
    ull r; asm("mov.b64 %0, {%1, %2};" : "=l"(r) : "f"(lo), "f"(hi)); return r;
}
__device__ __forceinline__ void unpack2(ull v, float& lo, float& hi) {
    asm("mov.b64 {%0, %1}, %2;" : "=f"(lo), "=f"(hi) : "l"(v));
}
__device__ __forceinline__ ull ffma2(ull a, ull b, ull c) {
    ull d; asm("fma.rn.f32x2 %0, %1, %2, %3;" : "=l"(d) : "l"(a), "l"(b), "l"(c)); return d;
}

// ---------------- one-time weight packing ----------------
__global__ __launch_bounds__(256) void k_pack(
    const float* __restrict__ pg_u, const float* __restrict__ lg_w,
    const float* __restrict__ lg_u, const float* __restrict__ pg_w,
    const float* __restrict__ att_w)
{
    int idx = blockIdx.x * 256 + threadIdx.x;
    if (idx < 512) {
        int q = idx >> 5, lane = idx & 31;
        g_u2z[idx] = pack2(pg_u[(2*q)*96 + lane],      pg_u[(2*q+1)*96 + lane]);
        g_u2r[idx] = pack2(pg_u[(2*q)*96 + 32 + lane], pg_u[(2*q+1)*96 + 32 + lane]);
        g_u2h[idx] = pack2(pg_u[(2*q)*96 + 64 + lane], pg_u[(2*q+1)*96 + 64 + lane]);
        g_aw2[idx] = pack2(att_w[(2*q)*32 + lane], att_w[(2*q+1)*32 + lane]);
    }
    int i2 = idx - 512;
    if (i2 >= 0 && i2 < 1536) {
        int jp = i2 / 96, c = i2 % 96;
        g_w2[i2] = pack2(lg_w[(2*jp)*96 + c], lg_w[(2*jp+1)*96 + c]);
        g_u2[i2] = pack2(lg_u[(2*jp)*96 + c], lg_u[(2*jp+1)*96 + c]);
        g_p2[i2] = pack2(pg_w[(2*jp)*96 + c], pg_w[(2*jp+1)*96 + c]);
    }
}

// ---------------- flow embedding ----------------
__global__ __launch_bounds__(256) void k_flow_embed(
    const float* __restrict__ tr, const float* __restrict__ ln,
    const float* __restrict__ lp, const float* __restrict__ pd,
    const float* __restrict__ w1, const float* __restrict__ b1,
    const float* __restrict__ w2, const float* __restrict__ b2)
{
    int w = threadIdx.x >> 5, lane = threadIdx.x & 31;
    int f = blockIdx.x * 8 + w;
    __shared__ __align__(16) float buf[8][32];
    float p0 = (tr[f] - 0.5f) * 2.0f;
    float p1 = (ln[f] - 0.5f) * 2.0f;
    float p2 = (lp[f] - 0.1f) * 5.0f;
    float p3 = (pd[f] - 0.2f) * 3.0f;
    float t1 = b1[lane];
    t1 = fmaf(p0, w1[lane],      t1);
    t1 = fmaf(p1, w1[32 + lane], t1);
    t1 = fmaf(p2, w1[64 + lane], t1);
    t1 = fmaf(p3, w1[96 + lane], t1);
    t1 = seluf(t1);
    buf[w][lane] = t1;
    __syncwarp();
    float o = b2[lane];
    #pragma unroll
    for (int j = 0; j < 32; j++) o = fmaf(buf[w][j], w2[j*32 + lane], o);
    g_path[f*32 + lane] = seluf(o);
}

// ---------------- link embedding ----------------
__global__ __launch_bounds__(256) void k_link_embed(
    const float* __restrict__ tr, const float* __restrict__ cap,
    const int* __restrict__ ffl,
    const float* __restrict__ w1, const float* __restrict__ b1,
    const float* __restrict__ w2, const float* __restrict__ b2)
{
    int w = threadIdx.x >> 5, lane = threadIdx.x & 31;
    int l = blockIdx.x * 8 + w;
    __shared__ __align__(16) float buf[8][32];
    float s = tr[ffl[l*64 + lane]] + tr[ffl[l*64 + 32 + lane]];
    #pragma unroll
    for (int sh = 16; sh > 0; sh >>= 1) s += __shfl_xor_sync(0xffffffffu, s, sh);
    float c = cap[l];
    float load = (s * (1.0f/64.0f)) / c;
    float p0 = (c - 1.0f);
    float t1 = b1[lane];
    t1 = fmaf(p0,   w1[lane],      t1);
    t1 = fmaf(load, w1[32 + lane], t1);
    t1 = seluf(t1);
    buf[w][lane] = t1;
    __syncwarp();
    float o = b2[lane];
    #pragma unroll
    for (int j = 0; j < 32; j++) o = fmaf(buf[w][j], w2[j*32 + lane], o);
    g_link[l*32 + lane] = seluf(o);
}

// ---------------- initial mlx = link_state @ pg_w + b0 ----------------
__global__ __launch_bounds__(256) void k_mlx(
    const float* __restrict__ pg_w, const float* __restrict__ pg_b)
{
    int w = threadIdx.x >> 5, lane = threadIdx.x & 31;
    int l = blockIdx.x * 8 + w;
    __shared__ __align__(16) float xbuf[8][32];
    float x = g_link[l*32 + lane];
    xbuf[w][lane] = x;
    __syncwarp();
    float az = pg_b[lane], ar = pg_b[32 + lane], ah = pg_b[64 + lane];
    #pragma unroll
    for (int j = 0; j < 32; j++) {
        float xj = xbuf[w][j];
        az = fmaf(xj, pg_w[j*96 + lane],      az);
        ar = fmaf(xj, pg_w[j*96 + 32 + lane], ar);
        ah = fmaf(xj, pg_w[j*96 + 64 + lane], ah);
    }
    g_mlx[l*96 + lane]      = az;
    g_mlx[l*96 + 32 + lane] = ar;
    g_mlx[l*96 + 64 + lane] = ah;
}

// ---------------- path GRU scan: 2 interleaved flows per warp ----------------
#define PAIRS 4   // pairs of flows per warp -> 8 flows/warp
__global__ __launch_bounds__(128) void k_path(
    const float* __restrict__ pg_b, const int* __restrict__ l2f)
{
    int w = threadIdx.x >> 5, lane = threadIdx.x & 31;
    __shared__ __align__(16) float hbuf[4][2][2][32];  // [warp][flow][buf][comp]

    ull u2z[16], u2r[16], u2h[16];
    #pragma unroll
    for (int q = 0; q < 16; q++) {
        u2z[q] = g_u2z[q*32 + lane];
        u2r[q] = g_u2r[q*32 + lane];
        u2h[q] = g_u2h[q*32 + lane];
    }
    ull b2z = pack2(pg_b[96 + lane], 0.f);
    ull b2r = pack2(pg_b[128 + lane], 0.f);
    ull b2h = pack2(pg_b[160 + lane], 0.f);

    int fbase = (blockIdx.x * 4 + w) * (2 * PAIRS);
    #pragma unroll 1
    for (int p = 0; p < PAIRS; p++) {
        int fA = fbase + 2*p, fB = fA + 1;
        int4 aA = ((const int4*)(l2f + fA*8))[0];
        int4 aB = ((const int4*)(l2f + fA*8))[1];
        int4 bA = ((const int4*)(l2f + fB*8))[0];
        int4 bB = ((const int4*)(l2f + fB*8))[1];
        int lidA[8] = {aA.x, aA.y, aA.z, aA.w, aB.x, aB.y, aB.z, aB.w};
        int lidB[8] = {bA.x, bA.y, bA.z, bA.w, bB.x, bB.y, bB.z, bB.w};
        float hA = g_path[fA*32 + lane];
        float hB = g_path[fB*32 + lane];
        float* pssA = g_pss + (size_t)fA * 9 * 32;
        float* pssB = g_pss + (size_t)fB * 9 * 32;
        pssA[lane] = hA;
        pssB[lane] = hB;
        hbuf[w][0][0][lane] = hA;
        hbuf[w][1][0][lane] = hB;
        const float* rA0 = g_mlx + lidA[0] * 96;
        const float* rA1 = g_mlx + lidA[1] * 96;
        const float* rB0 = g_mlx + lidB[0] * 96;
        const float* rB1 = g_mlx + lidB[1] * 96;
        float Amz0 = rA0[lane], Amr0 = rA0[32+lane], Amh0 = rA0[64+lane];
        float Bmz0 = rB0[lane], Bmr0 = rB0[32+lane], Bmh0 = rB0[64+lane];
        float Amz1 = rA1[lane], Amr1 = rA1[32+lane], Amh1 = rA1[64+lane];
        float Bmz1 = rB1[lane], Bmr1 = rB1[32+lane], Bmh1 = rB1[64+lane];
        __syncwarp();

        #pragma unroll
        for (int t = 0; t < 8; t++) {
            float Amz2, Amr2, Amh2, Bmz2, Bmr2, Bmh2;
            if (t < 6) {
                const float* nA = g_mlx + lidA[t+2] * 96;
                const float* nB = g_mlx + lidB[t+2] * 96;
                Amz2 = nA[lane]; Amr2 = nA[32+lane]; Amh2 = nA[64+lane];
                Bmz2 = nB[lane]; Bmr2 = nB[32+lane]; Bmh2 = nB[64+lane];
            }
            ull Aaz = b2z, Aar = b2r, Aah = b2h;
            ull Baz = b2z, Bar = b2r, Bah = b2h;
            const float* hbA = hbuf[w][0][t & 1];
            const float* hbB = hbuf[w][1][t & 1];
            #pragma unroll
            for (int q = 0; q < 8; q++) {
                ulonglong2 hvA = ((const ulonglong2*)hbA)[q];
                ulonglong2 hvB = ((const ulonglong2*)hbB)[q];
                Aaz = ffma2(hvA.x, u2z[2*q],   Aaz);
                Baz = ffma2(hvB.x, u2z[2*q],   Baz);
                Aar = ffma2(hvA.x, u2r[2*q],   Aar);
                Bar = ffma2(hvB.x, u2r[2*q],   Bar);
                Aah = ffma2(hvA.x, u2h[2*q],   Aah);
                Bah = ffma2(hvB.x, u2h[2*q],   Bah);
                Aaz = ffma2(hvA.y, u2z[2*q+1], Aaz);
                Baz = ffma2(hvB.y, u2z[2*q+1], Baz);
                Aar = ffma2(hvA.y, u2r[2*q+1], Aar);
                Bar = ffma2(hvB.y, u2r[2*q+1], Bar);
                Aah = ffma2(hvA.y, u2h[2*q+1], Aah);
                Bah = ffma2(hvB.y, u2h[2*q+1], Bah);
            }
            float lo, hi;
            unpack2(Aaz, lo, hi); float az_A = lo + hi;
            unpack2(Baz, lo, hi); float az_B = lo + hi;
            unpack2(Aar, lo, hi); float ar_A = lo + hi;
            unpack2(Bar, lo, hi); float ar_B = lo + hi;
            unpack2(Aah, lo, hi); float ah_A = lo + hi;
            unpack2(Bah, lo, hi); float ah_B = lo + hi;
            float zA = sigmoidf(Amz0 + az_A);
            float zB = sigmoidf(Bmz0 + az_B);
            float rA = sigmoidf(Amr0 + ar_A);
            float rB = sigmoidf(Bmr0 + ar_B);
            float cA = fast_tanh(Amh0 + rA * ah_A);
            float cB = fast_tanh(Bmh0 + rB * ah_B);
            hA = fmaf(zA, hA, (1.f - zA) * cA);
            hB = fmaf(zB, hB, (1.f - zB) * cB);
            pssA[(t+1)*32 + lane] = hA;
            pssB[(t+1)*32 + lane] = hB;
            hbuf[w][0][(t+1) & 1][lane] = hA;
            hbuf[w][1][(t+1) & 1][lane] = hB;
            __syncwarp();
            Amz0 = Amz1; Amr0 = Amr1; Amh0 = Amh1;
            Bmz0 = Bmz1; Bmr0 = Bmr1; Bmh0 = Bmh1;
            Amz1 = Amz2; Amr1 = Amr2; Amh1 = Amh2;
            Bmz1 = Bmz2; Bmr1 = Bmr2; Bmh1 = Bmh2;
        }
        g_path[fA*32 + lane] = hA;
        g_path[fB*32 + lane] = hB;
    }
}

// ---------------- link update: 2 warps per link (serial chain halved) ----------------
__global__ __launch_bounds__(256) void k_link(
    const float* __restrict__ att_b,
    const float* __restrict__ lg_b, const float* __restrict__ pg_b,
    const int* __restrict__ ffl, const int* __restrict__ fpos)
{
    int tid = threadIdx.x, lane = tid & 31, warp = tid >> 5;
    int li = warp >> 1;          // link slot within block: 0..3
    int half = warp & 1;         // which 32 of the 64 flows

    __shared__ __align__(16) float vbuf[8][2][4][32];  // [warp][buf][elem][comp]
    __shared__ __align__(16) float aggbuf[8][32];

    ull aw2[16];
    #pragma unroll
    for (int q = 0; q < 16; q++) aw2[q] = g_aw2[q*32 + lane];
    ull ab2 = pack2(att_b[lane], 0.f);

    int l = blockIdx.x * 4 + li;
    const int4* fr4 = (const int4*)(ffl  + l * 64) + half * 8;   // 8 groups of 4
    const int4* pr4 = (const int4*)(fpos + l * 64) + half * 8;

    // pipeline prologue: gathers for groups 0 and 1 in flight
    int4 fA = fr4[0], pA = pr4[0];
    float v0 = g_pss[((size_t)fA.x * 9 + pA.x) * 32 + lane];
    float v1 = g_pss[((size_t)fA.y * 9 + pA.y) * 32 + lane];
    float v2 = g_pss[((size_t)fA.z * 9 + pA.z) * 32 + lane];
    float v3 = g_pss[((size_t)fA.w * 9 + pA.w) * 32 + lane];
    int4 fB = fr4[1], pB = pr4[1];
    float w0 = g_pss[((size_t)fB.x * 9 + pB.x) * 32 + lane];
    float w1v = g_pss[((size_t)fB.y * 9 + pB.y) * 32 + lane];
    float w2v = g_pss[((size_t)fB.z * 9 + pB.z) * 32 + lane];
    float w3v = g_pss[((size_t)fB.w * 9 + pB.w) * 32 + lane];
    int4 fC = fr4[2], pC = pr4[2];

    float agg = 0.f;
    #pragma unroll 1
    for (int g = 0; g < 8; g++) {
        float n0 = 0.f, n1 = 0.f, n2 = 0.f, n3 = 0.f;
        if (g < 6) {
            n0 = g_pss[((size_t)fC.x * 9 + pC.x) * 32 + lane];
            n1 = g_pss[((size_t)fC.y * 9 + pC.y) * 32 + lane];
            n2 = g_pss[((size_t)fC.z * 9 + pC.z) * 32 + lane];
            n3 = g_pss[((size_t)fC.w * 9 + pC.w) * 32 + lane];
        }
        int4 fD, pD;
        if (g < 5) { fD = fr4[g+3]; pD = pr4[g+3]; }

        int b = g & 1;
        vbuf[warp][b][0][lane] = v0;
        vbuf[warp][b][1][lane] = v1;
        vbuf[warp][b][2][lane] = v2;
        vbuf[warp][b][3][lane] = v3;
        __syncwarp();

        ull a20 = ab2, a21 = ab2, a22 = ab2, a23 = ab2;
        #pragma unroll
        for (int q = 0; q < 8; q++) {
            ulonglong2 x0 = ((const ulonglong2*)vbuf[warp][b][0])[q];
            ulonglong2 x1 = ((const ulonglong2*)vbuf[warp][b][1])[q];
            ulonglong2 x2 = ((const ulonglong2*)vbuf[warp][b][2])[q];
            ulonglong2 x3 = ((const ulonglong2*)vbuf[warp][b][3])[q];
            a20 = ffma2(x0.x, aw2[2*q],   a20);
            a21 = ffma2(x1.x, aw2[2*q],   a21);
            a22 = ffma2(x2.x, aw2[2*q],   a22);
            a23 = ffma2(x3.x, aw2[2*q],   a23);
            a20 = ffma2(x0.y, aw2[2*q+1], a20);
            a21 = ffma2(x1.y, aw2[2*q+1], a21);
            a22 = ffma2(x2.y, aw2[2*q+1], a22);
            a23 = ffma2(x3.y, aw2[2*q+1], a23);
        }
        float lo, hi;
        unpack2(a20, lo, hi); float a0 = lo + hi;
        unpack2(a21, lo, hi); float a1 = lo + hi;
        unpack2(a22, lo, hi); float a2 = lo + hi;
        unpack2(a23, lo, hi); float a3 = lo + hi;
        a0 = a0 > 0.f ? a0 : 0.2f * a0;
        a1 = a1 > 0.f ? a1 : 0.2f * a1;
        a2 = a2 > 0.f ? a2 : 0.2f * a2;
        a3 = a3 > 0.f ? a3 : 0.2f * a3;
        float e0 = __expf(a0), e1 = __expf(a1), e2 = __expf(a2), e3 = __expf(a3);
        float s0 = e0, s1 = e1, s2 = e2, s3 = e3;
        #pragma unroll
        for (int sh = 16; sh > 0; sh >>= 1) {
            s0 += __shfl_xor_sync(0xffffffffu, s0, sh);
            s1 += __shfl_xor_sync(0xffffffffu, s1, sh);
            s2 += __shfl_xor_sync(0xffffffffu, s2, sh);
            s3 += __shfl_xor_sync(0xffffffffu, s3, sh);
        }
        agg = fmaf(__fdividef(e0, s0), v0, agg);
        agg = fmaf(__fdividef(e1, s1), v1, agg);
        agg = fmaf(__fdividef(e2, s2), v2, agg);
        agg = fmaf(__fdividef(e3, s3), v3, agg);
        v0 = w0;  v1 = w1v; v2 = w2v; v3 = w3v;
        w0 = n0;  w1v = n1; w2v = n2; w3v = n3;
        fC = fD;  pC = pD;
    }

    aggbuf[warp][lane] = agg;
    __syncthreads();

    if (half == 0) {
        // combine partials; GRU + fused mlx for this link (4 tails run concurrently)
        float x = aggbuf[2*li][lane] + aggbuf[2*li + 1][lane];
        float h = g_link[l*32 + lane];
        vbuf[warp][0][0][lane] = x;
        vbuf[warp][0][1][lane] = h;
        __syncwarp();
        ull az2 = pack2(lg_b[lane],       0.f);
        ull ar2 = pack2(lg_b[32 + lane],  0.f);
        ull ah2 = pack2(lg_b[64 + lane],  0.f);
        ull hz2 = pack2(lg_b[96 + lane],  0.f);
        ull hr2 = pack2(lg_b[128 + lane], 0.f);
        ull hh2 = pack2(lg_b[160 + lane], 0.f);
        #pragma unroll
        for (int jp = 0; jp < 16; jp++) {
            ull xj = ((const ull*)vbuf[warp][0][0])[jp];
            ull hj = ((const ull*)vbuf[warp][0][1])[jp];
            az2 = ffma2(xj, g_w2[jp*96 + lane],      az2);
            ar2 = ffma2(xj, g_w2[jp*96 + 32 + lane], ar2);
            ah2 = ffma2(xj, g_w2[jp*96 + 64 + lane], ah2);
            hz2 = ffma2(hj, g_u2[jp*96 + lane],      hz2);
            hr2 = ffma2(hj, g_u2[jp*96 + 32 + lane], hr2);
            hh2 = ffma2(hj, g_u2[jp*96 + 64 + lane], hh2);
        }
        float t0, t1v;
        unpack2(az2, t0, t1v); float az = t0 + t1v;
        unpack2(ar2, t0, t1v); float ar = t0 + t1v;
        unpack2(ah2, t0, t1v); float ah = t0 + t1v;
        unpack2(hz2, t0, t1v); float hz = t0 + t1v;
        unpack2(hr2, t0, t1v); float hr = t0 + t1v;
        unpack2(hh2, t0, t1v); float hh = t0 + t1v;
        float z = sigmoidf(az + hz);
        float r = sigmoidf(ar + hr);
        float c = fast_tanh(ah + r * hh);
        float hn = fmaf(z, h, (1.f - z) * c);
        g_link[l*32 + lane] = hn;

        // fused mlx for next iteration
        __syncwarp();
        vbuf[warp][0][0][lane] = hn;
        __syncwarp();
        ull mz2 = pack2(pg_b[lane],      0.f);
        ull mr2 = pack2(pg_b[32 + lane], 0.f);
        ull mh2 = pack2(pg_b[64 + lane], 0.f);
        #pragma unroll
        for (int jp = 0; jp < 16; jp++) {
            ull hj = ((const ull*)vbuf[warp][0][0])[jp];
            mz2 = ffma2(hj, g_p2[jp*96 + lane],      mz2);
            mr2 = ffma2(hj, g_p2[jp*96 + 32 + lane], mr2);
            mh2 = ffma2(hj, g_p2[jp*96 + 64 + lane], mh2);
        }
        unpack2(mz2, t0, t1v); g_mlx[l*96 + lane]      = t0 + t1v;
        unpack2(mr2, t0, t1v); g_mlx[l*96 + 32 + lane] = t0 + t1v;
        unpack2(mh2, t0, t1v); g_mlx[l*96 + 64 + lane] = t0 + t1v;
    }
}

// ---------------- readout ----------------
__global__ __launch_bounds__(256) void k_readout(
    const float* __restrict__ w1, const float* __restrict__ b1,
    const float* __restrict__ w2, const float* __restrict__ b2,
    const float* __restrict__ w3, const float* __restrict__ b3,
    const int* __restrict__ l2f, const float* __restrict__ cap,
    const float* __restrict__ pd, float* __restrict__ out)
{
    __shared__ float sw1[32*16];
    __shared__ float sw2[16*8];
    __shared__ float sw3[8];
    __shared__ float sb1[16], sb2[8];
    if (threadIdx.x < 32*16) sw1[threadIdx.x] = w1[threadIdx.x];
    if (threadIdx.x < 16*8)  sw2[threadIdx.x] = w2[threadIdx.x];
    if (threadIdx.x < 8)     sw3[threadIdx.x] = w3[threadIdx.x];
    if (threadIdx.x < 16)    sb1[threadIdx.x] = b1[threadIdx.x];
    if (threadIdx.x < 8)     sb2[threadIdx.x] = b2[threadIdx.x];
    __syncthreads();

    int tid = blockIdx.x * 256 + threadIdx.x;
    int f = tid >> 3, t = tid & 7;

    float s[32];
    const float4* row = (const float4*)(g_pss + ((size_t)f * 9 + (t + 1)) * 32);
    #pragma unroll
    for (int i = 0; i < 8; i++) {
        float4 v = row[i];
        s[4*i] = v.x; s[4*i+1] = v.y; s[4*i+2] = v.z; s[4*i+3] = v.w;
    }
    float h1[16];
    #pragma unroll
    for (int k = 0; k < 16; k++) {
        float a = sb1[k];
        #pragma unroll
        for (int j = 0; j < 32; j++) a = fmaf(s[j], sw1[j*16 + k], a);
        h1[k] = seluf(a);
    }
    float h2[8];
    #pragma unroll
    for (int k = 0; k < 8; k++) {
        float a = sb2[k];
        #pragma unroll
        for (int j = 0; j < 16; j++) a = fmaf(h1[j], sw2[j*8 + k], a);
        h2[k] = seluf(a);
    }
    float o = b3[0];
    #pragma unroll
    for (int j = 0; j < 8; j++) o = fmaf(h2[j], sw3[j], o);
    float occ = fmaxf(o, 0.f) + log1pf(__expf(-fabsf(o)));   // softplus, stable
    float c = cap[l2f[f*8 + t]];
    float val = occ / c;
    val += __shfl_xor_sync(0xffffffffu, val, 1);
    val += __shfl_xor_sync(0xffffffffu, val, 2);
    val += __shfl_xor_sync(0xffffffffu, val, 4);
    if (t == 0) out[f] = val + pd[f];
}

// ---------------- launch ----------------
extern "C" void kernel_launch(void* const* d_in, const int* in_sizes, int n_in,
                              void* d_out, int out_size)
{
    const float* flow_traffic = (const float*)d_in[0];
    const float* flow_length  = (const float*)d_in[1];
    const float* flow_loss    = (const float*)d_in[2];
    const float* flow_pdelay  = (const float*)d_in[3];
    /* d_in[4] flow_packet_size unused */
    const float* link_cap     = (const float*)d_in[5];
    const int*   l2f          = (const int*)d_in[6];
    const int*   ffl          = (const int*)d_in[7];
    const int*   fpos         = (const int*)d_in[8];
    const float* fe_w1 = (const float*)d_in[9];
    const float* fe_b1 = (const float*)d_in[10];
    const float* fe_w2 = (const float*)d_in[11];
    const float* fe_b2 = (const float*)d_in[12];
    const float* le_w1 = (const float*)d_in[13];
    const float* le_b1 = (const float*)d_in[14];
    const float* le_w2 = (const float*)d_in[15];
    const float* le_b2 = (const float*)d_in[16];
    const float* att_w = (const float*)d_in[17];
    const float* att_b = (const float*)d_in[18];
    const float* pg_w  = (const float*)d_in[19];
    const float* pg_u  = (const float*)d_in[20];
    const float* pg_b  = (const float*)d_in[21];
    const float* lg_w  = (const float*)d_in[22];
    const float* lg_u  = (const float*)d_in[23];
    const float* lg_b  = (const float*)d_in[24];
    const float* ro_w1 = (const float*)d_in[25];
    const float* ro_b1 = (const float*)d_in[26];
    const float* ro_w2 = (const float*)d_in[27];
    const float* ro_b2 = (const float*)d_in[28];
    const float* ro_w3 = (const float*)d_in[29];
    const float* ro_b3 = (const float*)d_in[30];
    float* out = (float*)d_out;

    k_pack<<<8, 256>>>(pg_u, lg_w, lg_u, pg_w, att_w);
    k_flow_embed<<<F_N/8, 256>>>(flow_traffic, flow_length, flow_loss, flow_pdelay,
                                 fe_w1, fe_b1, fe_w2, fe_b2);
    k_link_embed<<<NLNK/8, 256>>>(flow_traffic, link_cap, ffl,
                                  le_w1, le_b1, le_w2, le_b2);
    k_mlx<<<NLNK/8, 256>>>(pg_w, pg_b);   // initial mlx; later ones fused in k_link
    for (int it = 0; it < NITER; it++) {
        k_path<<<F_N/(4*2*PAIRS), 128>>>(pg_b, l2f);
        k_link<<<NLNK/4, 256>>>(att_b, lg_b, pg_b, ffl, fpos);
    }
    k_readout<<<(F_N*LPL)/256, 256>>>(ro_w1, ro_b1, ro_w2, ro_b2, ro_w3, ro_b3,
                                      l2f, link_cap, flow_pdelay, out);
}

// round 11
// speedup vs baseline: 1.0929x; 1.0929x over previous
#include <cuda_runtime.h>
#include <cstdint>
#include <stdint.h>
#include <math.h>

#define F_N   65536
#define LPL   8
#define NLNK  8192
#define DGD   64
#define DD    32
#define NITER 8

typedef unsigned long long ull;

// ---------------- device scratch (no allocations allowed) ----------------
__device__ float g_path[F_N * DD];            // 8 MB   path_state
__device__ float g_link[NLNK * DD];           // 1 MB   link_state
__device__ float g_mlx [NLNK * 96];           // 3 MB   link_state @ pg_w + b0
__device__ float g_pss [(size_t)F_N * 9 * DD];// 75.5MB [F,9,32]
// packed (pair-along-j) weights, computed once per run (in k_setup)
__device__ ull g_u2z[16*32], g_u2r[16*32], g_u2h[16*32];  // path GRU U
__device__ ull g_w2[16*96], g_u2[16*96], g_p2[16*96];     // link GRU W/U + pg_w
__device__ ull g_aw2[16*32];                              // att_w

// ---------------- math helpers ----------------
__device__ __forceinline__ float seluf(float x) {
    const float sc = 1.0507009873554804934f;
    const float al = 1.6732632423543772848f;
    return x > 0.f ? sc * x : sc * al * expm1f(x);
}
__device__ __forceinline__ float sigmoidf(float x) {
    return __fdividef(1.0f, 1.0f + __expf(-x));
}
__device__ __forceinline__ float fast_tanh(float x) {
    float e = __expf(2.0f * x);
    return 1.0f - __fdividef(2.0f, e + 1.0f);
}
__device__ __forceinline__ ull pack2(float lo, float hi) {
    ull r; asm("mov.b64 %0, {%1, %2};" : "=l"(r) : "f"(lo), "f"(hi)); return r;
}
__device__ __forceinline__ void unpack2(ull v, float& lo, float& hi) {
    asm("mov.b64 {%0, %1}, %2;" : "=f"(lo), "=f"(hi) : "l"(v));
}
__device__ __forceinline__ ull ffma2(ull a, ull b, ull c) {
    ull d; asm("fma.rn.f32x2 %0, %1, %2, %3;" : "=l"(d) : "l"(a), "l"(b), "l"(c)); return d;
}

// ---------------- fused setup: flow embed + link embed + weight pack ----------------
// blocks [0, F_N/8)                : flow embedding (8 flows/block)
// blocks [F_N/8, F_N/8+NLNK/8)     : link embedding (8 links/block)
// blocks [F_N/8+NLNK/8, +8)        : weight packing
#define SETUP_FLOW_BLOCKS (F_N/8)
#define SETUP_LINK_BLOCKS (NLNK/8)
#define SETUP_PACK_BLOCKS 8
#define SETUP_BLOCKS (SETUP_FLOW_BLOCKS + SETUP_LINK_BLOCKS + SETUP_PACK_BLOCKS)
__global__ __launch_bounds__(256) void k_setup(
    const float* __restrict__ tr, const float* __restrict__ ln,
    const float* __restrict__ lp, const float* __restrict__ pd,
    const float* __restrict__ cap, const int* __restrict__ ffl,
    const float* __restrict__ fe_w1, const float* __restrict__ fe_b1,
    const float* __restrict__ fe_w2, const float* __restrict__ fe_b2,
    const float* __restrict__ le_w1, const float* __restrict__ le_b1,
    const float* __restrict__ le_w2, const float* __restrict__ le_b2,
    const float* __restrict__ pg_u, const float* __restrict__ lg_w,
    const float* __restrict__ lg_u, const float* __restrict__ pg_w,
    const float* __restrict__ att_w)
{
    int w = threadIdx.x >> 5, lane = threadIdx.x & 31;
    __shared__ __align__(16) float buf[8][32];

    if (blockIdx.x < SETUP_FLOW_BLOCKS) {
        int f = blockIdx.x * 8 + w;
        float p0 = (tr[f] - 0.5f) * 2.0f;
        float p1 = (ln[f] - 0.5f) * 2.0f;
        float p2 = (lp[f] - 0.1f) * 5.0f;
        float p3 = (pd[f] - 0.2f) * 3.0f;
        float t1 = fe_b1[lane];
        t1 = fmaf(p0, fe_w1[lane],      t1);
        t1 = fmaf(p1, fe_w1[32 + lane], t1);
        t1 = fmaf(p2, fe_w1[64 + lane], t1);
        t1 = fmaf(p3, fe_w1[96 + lane], t1);
        t1 = seluf(t1);
        buf[w][lane] = t1;
        __syncwarp();
        float o = fe_b2[lane];
        #pragma unroll
        for (int j = 0; j < 32; j++) o = fmaf(buf[w][j], fe_w2[j*32 + lane], o);
        g_path[f*32 + lane] = seluf(o);
    } else if (blockIdx.x < SETUP_FLOW_BLOCKS + SETUP_LINK_BLOCKS) {
        int l = (blockIdx.x - SETUP_FLOW_BLOCKS) * 8 + w;
        float s = tr[ffl[l*64 + lane]] + tr[ffl[l*64 + 32 + lane]];
        #pragma unroll
        for (int sh = 16; sh > 0; sh >>= 1) s += __shfl_xor_sync(0xffffffffu, s, sh);
        float c = cap[l];
        float load = (s * (1.0f/64.0f)) / c;
        float p0 = (c - 1.0f);
        float t1 = le_b1[lane];
        t1 = fmaf(p0,   le_w1[lane],      t1);
        t1 = fmaf(load, le_w1[32 + lane], t1);
        t1 = seluf(t1);
        buf[w][lane] = t1;
        __syncwarp();
        float o = le_b2[lane];
        #pragma unroll
        for (int j = 0; j < 32; j++) o = fmaf(buf[w][j], le_w2[j*32 + lane], o);
        g_link[l*32 + lane] = seluf(o);
    } else {
        int idx = (blockIdx.x - SETUP_FLOW_BLOCKS - SETUP_LINK_BLOCKS) * 256 + threadIdx.x;
        if (idx < 512) {
            int q = idx >> 5, la = idx & 31;
            g_u2z[idx] = pack2(pg_u[(2*q)*96 + la],      pg_u[(2*q+1)*96 + la]);
            g_u2r[idx] = pack2(pg_u[(2*q)*96 + 32 + la], pg_u[(2*q+1)*96 + 32 + la]);
            g_u2h[idx] = pack2(pg_u[(2*q)*96 + 64 + la], pg_u[(2*q+1)*96 + 64 + la]);
            g_aw2[idx] = pack2(att_w[(2*q)*32 + la], att_w[(2*q+1)*32 + la]);
        }
        int i2 = idx - 512;
        if (i2 >= 0 && i2 < 1536) {
            int jp = i2 / 96, c = i2 % 96;
            g_w2[i2] = pack2(lg_w[(2*jp)*96 + c], lg_w[(2*jp+1)*96 + c]);
            g_u2[i2] = pack2(lg_u[(2*jp)*96 + c], lg_u[(2*jp+1)*96 + c]);
            g_p2[i2] = pack2(pg_w[(2*jp)*96 + c], pg_w[(2*jp+1)*96 + c]);
        }
    }
}

// ---------------- initial mlx = link_state @ pg_w + b0 ----------------
__global__ __launch_bounds__(256) void k_mlx(
    const float* __restrict__ pg_w, const float* __restrict__ pg_b)
{
    int w = threadIdx.x >> 5, lane = threadIdx.x & 31;
    int l = blockIdx.x * 8 + w;
    __shared__ __align__(16) float xbuf[8][32];
    float x = g_link[l*32 + lane];
    xbuf[w][lane] = x;
    __syncwarp();
    float az = pg_b[lane], ar = pg_b[32 + lane], ah = pg_b[64 + lane];
    #pragma unroll
    for (int j = 0; j < 32; j++) {
        float xj = xbuf[w][j];
        az = fmaf(xj, pg_w[j*96 + lane],      az);
        ar = fmaf(xj, pg_w[j*96 + 32 + lane], ar);
        ah = fmaf(xj, pg_w[j*96 + 64 + lane], ah);
    }
    g_mlx[l*96 + lane]      = az;
    g_mlx[l*96 + 32 + lane] = ar;
    g_mlx[l*96 + 64 + lane] = ah;
}

// ---------------- path GRU scan: 2 interleaved flows per warp ----------------
#define PAIRS 4   // pairs of flows per warp -> 8 flows/warp
__global__ __launch_bounds__(128) void k_path(
    const float* __restrict__ pg_b, const int* __restrict__ l2f)
{
    int w = threadIdx.x >> 5, lane = threadIdx.x & 31;
    __shared__ __align__(16) float hbuf[4][2][2][32];  // [warp][flow][buf][comp]

    ull u2z[16], u2r[16], u2h[16];
    #pragma unroll
    for (int q = 0; q < 16; q++) {
        u2z[q] = g_u2z[q*32 + lane];
        u2r[q] = g_u2r[q*32 + lane];
        u2h[q] = g_u2h[q*32 + lane];
    }
    ull b2z = pack2(pg_b[96 + lane], 0.f);
    ull b2r = pack2(pg_b[128 + lane], 0.f);
    ull b2h = pack2(pg_b[160 + lane], 0.f);

    int fbase = (blockIdx.x * 4 + w) * (2 * PAIRS);
    #pragma unroll 1
    for (int p = 0; p < PAIRS; p++) {
        int fA = fbase + 2*p, fB = fA + 1;
        int4 aA = ((const int4*)(l2f + fA*8))[0];
        int4 aB = ((const int4*)(l2f + fA*8))[1];
        int4 bA = ((const int4*)(l2f + fB*8))[0];
        int4 bB = ((const int4*)(l2f + fB*8))[1];
        int lidA[8] = {aA.x, aA.y, aA.z, aA.w, aB.x, aB.y, aB.z, aB.w};
        int lidB[8] = {bA.x, bA.y, bA.z, bA.w, bB.x, bB.y, bB.z, bB.w};
        float hA = g_path[fA*32 + lane];
        float hB = g_path[fB*32 + lane];
        float* pssA = g_pss + (size_t)fA * 9 * 32;
        float* pssB = g_pss + (size_t)fB * 9 * 32;
        pssA[lane] = hA;
        pssB[lane] = hB;
        hbuf[w][0][0][lane] = hA;
        hbuf[w][1][0][lane] = hB;
        const float* rA0 = g_mlx + lidA[0] * 96;
        const float* rA1 = g_mlx + lidA[1] * 96;
        const float* rB0 = g_mlx + lidB[0] * 96;
        const float* rB1 = g_mlx + lidB[1] * 96;
        float Amz0 = rA0[lane], Amr0 = rA0[32+lane], Amh0 = rA0[64+lane];
        float Bmz0 = rB0[lane], Bmr0 = rB0[32+lane], Bmh0 = rB0[64+lane];
        float Amz1 = rA1[lane], Amr1 = rA1[32+lane], Amh1 = rA1[64+lane];
        float Bmz1 = rB1[lane], Bmr1 = rB1[32+lane], Bmh1 = rB1[64+lane];
        __syncwarp();

        #pragma unroll
        for (int t = 0; t < 8; t++) {
            float Amz2, Amr2, Amh2, Bmz2, Bmr2, Bmh2;
            if (t < 6) {
                const float* nA = g_mlx + lidA[t+2] * 96;
                const float* nB = g_mlx + lidB[t+2] * 96;
                Amz2 = nA[lane]; Amr2 = nA[32+lane]; Amh2 = nA[64+lane];
                Bmz2 = nB[lane]; Bmr2 = nB[32+lane]; Bmh2 = nB[64+lane];
            }
            ull Aaz = b2z, Aar = b2r, Aah = b2h;
            ull Baz = b2z, Bar = b2r, Bah = b2h;
            const float* hbA = hbuf[w][0][t & 1];
            const float* hbB = hbuf[w][1][t & 1];
            #pragma unroll
            for (int q = 0; q < 8; q++) {
                ulonglong2 hvA = ((const ulonglong2*)hbA)[q];
                ulonglong2 hvB = ((const ulonglong2*)hbB)[q];
                Aaz = ffma2(hvA.x, u2z[2*q],   Aaz);
                Baz = ffma2(hvB.x, u2z[2*q],   Baz);
                Aar = ffma2(hvA.x, u2r[2*q],   Aar);
                Bar = ffma2(hvB.x, u2r[2*q],   Bar);
                Aah = ffma2(hvA.x, u2h[2*q],   Aah);
                Bah = ffma2(hvB.x, u2h[2*q],   Bah);
                Aaz = ffma2(hvA.y, u2z[2*q+1], Aaz);
                Baz = ffma2(hvB.y, u2z[2*q+1], Baz);
                Aar = ffma2(hvA.y, u2r[2*q+1], Aar);
                Bar = ffma2(hvB.y, u2r[2*q+1], Bar);
                Aah = ffma2(hvA.y, u2h[2*q+1], Aah);
                Bah = ffma2(hvB.y, u2h[2*q+1], Bah);
            }
            float lo, hi;
            unpack2(Aaz, lo, hi); float az_A = lo + hi;
            unpack2(Baz, lo, hi); float az_B = lo + hi;
            unpack2(Aar, lo, hi); float ar_A = lo + hi;
            unpack2(Bar, lo, hi); float ar_B = lo + hi;
            unpack2(Aah, lo, hi); float ah_A = lo + hi;
            unpack2(Bah, lo, hi); float ah_B = lo + hi;
            float zA = sigmoidf(Amz0 + az_A);
            float zB = sigmoidf(Bmz0 + az_B);
            float rA = sigmoidf(Amr0 + ar_A);
            float rB = sigmoidf(Bmr0 + ar_B);
            float cA = fast_tanh(Amh0 + rA * ah_A);
            float cB = fast_tanh(Bmh0 + rB * ah_B);
            hA = fmaf(zA, hA, (1.f - zA) * cA);
            hB = fmaf(zB, hB, (1.f - zB) * cB);
            pssA[(t+1)*32 + lane] = hA;
            pssB[(t+1)*32 + lane] = hB;
            hbuf[w][0][(t+1) & 1][lane] = hA;
            hbuf[w][1][(t+1) & 1][lane] = hB;
            __syncwarp();
            Amz0 = Amz1; Amr0 = Amr1; Amh0 = Amh1;
            Bmz0 = Bmz1; Bmr0 = Bmr1; Bmh0 = Bmh1;
            Amz1 = Amz2; Amr1 = Amr2; Amh1 = Amh2;
            Bmz1 = Bmz2; Bmr1 = Bmr2; Bmh1 = Bmh2;
        }
        g_path[fA*32 + lane] = hA;
        g_path[fB*32 + lane] = hB;
    }
}

// ---------------- link update: warp-per-link, 4-wide, 3-deep gather pipe ----------------
__global__ __launch_bounds__(256) void k_link(
    const float* __restrict__ att_b,
    const float* __restrict__ lg_b, const float* __restrict__ pg_b,
    const int* __restrict__ ffl, const int* __restrict__ fpos)
{
    int tid = threadIdx.x, lane = tid & 31, warp = tid >> 5;

    __shared__ __align__(16) float vbuf[8][2][4][32];

    ull aw2[16];
    #pragma unroll
    for (int q = 0; q < 16; q++) aw2[q] = g_aw2[q*32 + lane];
    ull ab2 = pack2(att_b[lane], 0.f);

    int l = blockIdx.x * 8 + warp;
    const int4* fr4 = (const int4*)(ffl  + l * 64);
    const int4* pr4 = (const int4*)(fpos + l * 64);

    // 3-deep pipeline prologue: gathers for groups 0,1,2 in flight
    int4 fA = fr4[0], pA = pr4[0];
    float v0 = g_pss[((size_t)fA.x * 9 + pA.x) * 32 + lane];
    float v1 = g_pss[((size_t)fA.y * 9 + pA.y) * 32 + lane];
    float v2 = g_pss[((size_t)fA.z * 9 + pA.z) * 32 + lane];
    float v3 = g_pss[((size_t)fA.w * 9 + pA.w) * 32 + lane];
    int4 fB = fr4[1], pB = pr4[1];
    float w0 = g_pss[((size_t)fB.x * 9 + pB.x) * 32 + lane];
    float w1v = g_pss[((size_t)fB.y * 9 + pB.y) * 32 + lane];
    float w2v = g_pss[((size_t)fB.z * 9 + pB.z) * 32 + lane];
    float w3v = g_pss[((size_t)fB.w * 9 + pB.w) * 32 + lane];
    int4 fB2 = fr4[2], pB2 = pr4[2];
    float x0 = g_pss[((size_t)fB2.x * 9 + pB2.x) * 32 + lane];
    float x1 = g_pss[((size_t)fB2.y * 9 + pB2.y) * 32 + lane];
    float x2 = g_pss[((size_t)fB2.z * 9 + pB2.z) * 32 + lane];
    float x3 = g_pss[((size_t)fB2.w * 9 + pB2.w) * 32 + lane];
    int4 fC = fr4[3], pC = pr4[3];

    float agg = 0.f;
    #pragma unroll 1
    for (int g = 0; g < 16; g++) {
        // issue gathers for group g+3
        float n0 = 0.f, n1 = 0.f, n2 = 0.f, n3 = 0.f;
        if (g < 13) {
            n0 = g_pss[((size_t)fC.x * 9 + pC.x) * 32 + lane];
            n1 = g_pss[((size_t)fC.y * 9 + pC.y) * 32 + lane];
            n2 = g_pss[((size_t)fC.z * 9 + pC.z) * 32 + lane];
            n3 = g_pss[((size_t)fC.w * 9 + pC.w) * 32 + lane];
        }
        int4 fD, pD;
        if (g < 12) { fD = fr4[g+4]; pD = pr4[g+4]; }

        int b = g & 1;
        vbuf[warp][b][0][lane] = v0;
        vbuf[warp][b][1][lane] = v1;
        vbuf[warp][b][2][lane] = v2;
        vbuf[warp][b][3][lane] = v3;
        __syncwarp();

        ull a20 = ab2, a21 = ab2, a22 = ab2, a23 = ab2;
        #pragma unroll
        for (int q = 0; q < 8; q++) {
            ulonglong2 y0 = ((const ulonglong2*)vbuf[warp][b][0])[q];
            ulonglong2 y1 = ((const ulonglong2*)vbuf[warp][b][1])[q];
            ulonglong2 y2 = ((const ulonglong2*)vbuf[warp][b][2])[q];
            ulonglong2 y3 = ((const ulonglong2*)vbuf[warp][b][3])[q];
            a20 = ffma2(y0.x, aw2[2*q],   a20);
            a21 = ffma2(y1.x, aw2[2*q],   a21);
            a22 = ffma2(y2.x, aw2[2*q],   a22);
            a23 = ffma2(y3.x, aw2[2*q],   a23);
            a20 = ffma2(y0.y, aw2[2*q+1], a20);
            a21 = ffma2(y1.y, aw2[2*q+1], a21);
            a22 = ffma2(y2.y, aw2[2*q+1], a22);
            a23 = ffma2(y3.y, aw2[2*q+1], a23);
        }
        float lo, hi;
        unpack2(a20, lo, hi); float a0 = lo + hi;
        unpack2(a21, lo, hi); float a1 = lo + hi;
        unpack2(a22, lo, hi); float a2 = lo + hi;
        unpack2(a23, lo, hi); float a3 = lo + hi;
        a0 = a0 > 0.f ? a0 : 0.2f * a0;
        a1 = a1 > 0.f ? a1 : 0.2f * a1;
        a2 = a2 > 0.f ? a2 : 0.2f * a2;
        a3 = a3 > 0.f ? a3 : 0.2f * a3;
        float e0 = __expf(a0), e1 = __expf(a1), e2 = __expf(a2), e3 = __expf(a3);
        float s0 = e0, s1 = e1, s2 = e2, s3 = e3;
        #pragma unroll
        for (int sh = 16; sh > 0; sh >>= 1) {
            s0 += __shfl_xor_sync(0xffffffffu, s0, sh);
            s1 += __shfl_xor_sync(0xffffffffu, s1, sh);
            s2 += __shfl_xor_sync(0xffffffffu, s2, sh);
            s3 += __shfl_xor_sync(0xffffffffu, s3, sh);
        }
        agg = fmaf(__fdividef(e0, s0), v0, agg);
        agg = fmaf(__fdividef(e1, s1), v1, agg);
        agg = fmaf(__fdividef(e2, s2), v2, agg);
        agg = fmaf(__fdividef(e3, s3), v3, agg);
        v0 = w0;  v1 = w1v; v2 = w2v; v3 = w3v;
        w0 = x0;  w1v = x1; w2v = x2; w3v = x3;
        x0 = n0;  x1 = n1;  x2 = n2;  x3 = n3;
        fC = fD;  pC = pD;
    }

    // ---- link GRU (packed weights straight from gmem, L1/L2-hit) ----
    __syncwarp();
    float h = g_link[l*32 + lane];
    vbuf[warp][0][0][lane] = agg;
    vbuf[warp][0][1][lane] = h;
    __syncwarp();
    ull az2 = pack2(lg_b[lane],       0.f);
    ull ar2 = pack2(lg_b[32 + lane],  0.f);
    ull ah2 = pack2(lg_b[64 + lane],  0.f);
    ull hz2 = pack2(lg_b[96 + lane],  0.f);
    ull hr2 = pack2(lg_b[128 + lane], 0.f);
    ull hh2 = pack2(lg_b[160 + lane], 0.f);
    #pragma unroll
    for (int jp = 0; jp < 16; jp++) {
        ull xj = ((const ull*)vbuf[warp][0][0])[jp];
        ull hj = ((const ull*)vbuf[warp][0][1])[jp];
        az2 = ffma2(xj, g_w2[jp*96 + lane],      az2);
        ar2 = ffma2(xj, g_w2[jp*96 + 32 + lane], ar2);
        ah2 = ffma2(xj, g_w2[jp*96 + 64 + lane], ah2);
        hz2 = ffma2(hj, g_u2[jp*96 + lane],      hz2);
        hr2 = ffma2(hj, g_u2[jp*96 + 32 + lane], hr2);
        hh2 = ffma2(hj, g_u2[jp*96 + 64 + lane], hh2);
    }
    float t0, t1v;
    unpack2(az2, t0, t1v); float az = t0 + t1v;
    unpack2(ar2, t0, t1v); float ar = t0 + t1v;
    unpack2(ah2, t0, t1v); float ah = t0 + t1v;
    unpack2(hz2, t0, t1v); float hz = t0 + t1v;
    unpack2(hr2, t0, t1v); float hr = t0 + t1v;
    unpack2(hh2, t0, t1v); float hh = t0 + t1v;
    float z = sigmoidf(az + hz);
    float r = sigmoidf(ar + hr);
    float c = fast_tanh(ah + r * hh);
    float hn = fmaf(z, h, (1.f - z) * c);
    g_link[l*32 + lane] = hn;

    // ---- fused mlx for next iteration ----
    __syncwarp();
    vbuf[warp][0][0][lane] = hn;
    __syncwarp();
    ull mz2 = pack2(pg_b[lane],      0.f);
    ull mr2 = pack2(pg_b[32 + lane], 0.f);
    ull mh2 = pack2(pg_b[64 + lane], 0.f);
    #pragma unroll
    for (int jp = 0; jp < 16; jp++) {
        ull hj = ((const ull*)vbuf[warp][0][0])[jp];
        mz2 = ffma2(hj, g_p2[jp*96 + lane],      mz2);
        mr2 = ffma2(hj, g_p2[jp*96 + 32 + lane], mr2);
        mh2 = ffma2(hj, g_p2[jp*96 + 64 + lane], mh2);
    }
    unpack2(mz2, t0, t1v); g_mlx[l*96 + lane]      = t0 + t1v;
    unpack2(mr2, t0, t1v); g_mlx[l*96 + 32 + lane] = t0 + t1v;
    unpack2(mh2, t0, t1v); g_mlx[l*96 + 64 + lane] = t0 + t1v;
}

// ---------------- readout ----------------
__global__ __launch_bounds__(256) void k_readout(
    const float* __restrict__ w1, const float* __restrict__ b1,
    const float* __restrict__ w2, const float* __restrict__ b2,
    const float* __restrict__ w3, const float* __restrict__ b3,
    const int* __restrict__ l2f, const float* __restrict__ cap,
    const float* __restrict__ pd, float* __restrict__ out)
{
    __shared__ float sw1[32*16];
    __shared__ float sw2[16*8];
    __shared__ float sw3[8];
    __shared__ float sb1[16], sb2[8];
    if (threadIdx.x < 32*16) sw1[threadIdx.x] = w1[threadIdx.x];
    if (threadIdx.x < 16*8)  sw2[threadIdx.x] = w2[threadIdx.x];
    if (threadIdx.x < 8)     sw3[threadIdx.x] = w3[threadIdx.x];
    if (threadIdx.x < 16)    sb1[threadIdx.x] = b1[threadIdx.x];
    if (threadIdx.x < 8)     sb2[threadIdx.x] = b2[threadIdx.x];
    __syncthreads();

    int tid = blockIdx.x * 256 + threadIdx.x;
    int f = tid >> 3, t = tid & 7;

    float s[32];
    const float4* row = (const float4*)(g_pss + ((size_t)f * 9 + (t + 1)) * 32);
    #pragma unroll
    for (int i = 0; i < 8; i++) {
        float4 v = row[i];
        s[4*i] = v.x; s[4*i+1] = v.y; s[4*i+2] = v.z; s[4*i+3] = v.w;
    }
    float h1[16];
    #pragma unroll
    for (int k = 0; k < 16; k++) {
        float a = sb1[k];
        #pragma unroll
        for (int j = 0; j < 32; j++) a = fmaf(s[j], sw1[j*16 + k], a);
        h1[k] = seluf(a);
    }
    float h2[8];
    #pragma unroll
    for (int k = 0; k < 8; k++) {
        float a = sb2[k];
        #pragma unroll
        for (int j = 0; j < 16; j++) a = fmaf(h1[j], sw2[j*8 + k], a);
        h2[k] = seluf(a);
    }
    float o = b3[0];
    #pragma unroll
    for (int j = 0; j < 8; j++) o = fmaf(h2[j], sw3[j], o);
    float occ = fmaxf(o, 0.f) + log1pf(__expf(-fabsf(o)));   // softplus, stable
    float c = cap[l2f[f*8 + t]];
    float val = occ / c;
    val += __shfl_xor_sync(0xffffffffu, val, 1);
    val += __shfl_xor_sync(0xffffffffu, val, 2);
    val += __shfl_xor_sync(0xffffffffu, val, 4);
    if (t == 0) out[f] = val + pd[f];
}

// ---------------- launch ----------------
extern "C" void kernel_launch(void* const* d_in, const int* in_sizes, int n_in,
                              void* d_out, int out_size)
{
    const float* flow_traffic = (const float*)d_in[0];
    const float* flow_length  = (const float*)d_in[1];
    const float* flow_loss    = (const float*)d_in[2];
    const float* flow_pdelay  = (const float*)d_in[3];
    /* d_in[4] flow_packet_size unused */
    const float* link_cap     = (const float*)d_in[5];
    const int*   l2f          = (const int*)d_in[6];
    const int*   ffl          = (const int*)d_in[7];
    const int*   fpos         = (const int*)d_in[8];
    const float* fe_w1 = (const float*)d_in[9];
    const float* fe_b1 = (const float*)d_in[10];
    const float* fe_w2 = (const float*)d_in[11];
    const float* fe_b2 = (const float*)d_in[12];
    const float* le_w1 = (const float*)d_in[13];
    const float* le_b1 = (const float*)d_in[14];
    const float* le_w2 = (const float*)d_in[15];
    const float* le_b2 = (const float*)d_in[16];
    const float* att_w = (const float*)d_in[17];
    const float* att_b = (const float*)d_in[18];
    const float* pg_w  = (const float*)d_in[19];
    const float* pg_u  = (const float*)d_in[20];
    const float* pg_b  = (const float*)d_in[21];
    const float* lg_w  = (const float*)d_in[22];
    const float* lg_u  = (const float*)d_in[23];
    const float* lg_b  = (const float*)d_in[24];
    const float* ro_w1 = (const float*)d_in[25];
    const float* ro_b1 = (const float*)d_in[26];
    const float* ro_w2 = (const float*)d_in[27];
    const float* ro_b2 = (const float*)d_in[28];
    const float* ro_w3 = (const float*)d_in[29];
    const float* ro_b3 = (const float*)d_in[30];
    float* out = (float*)d_out;

    // launch order matters: ncu captures launch #4 -> k_link (1st iteration)
    k_setup<<<SETUP_BLOCKS, 256>>>(flow_traffic, flow_length, flow_loss, flow_pdelay,
                                   link_cap, ffl,
                                   fe_w1, fe_b1, fe_w2, fe_b2,
                                   le_w1, le_b1, le_w2, le_b2,
                                   pg_u, lg_w, lg_u, pg_w, att_w);
    k_mlx<<<NLNK/8, 256>>>(pg_w, pg_b);   // initial mlx; later ones fused in k_link
    for (int it = 0; it < NITER; it++) {
        k_path<<<F_N/(4*2*PAIRS), 128>>>(pg_b, l2f);
        k_link<<<NLNK/8, 256>>>(att_b, lg_b, pg_b, ffl, fpos);
    }
    k_readout<<<(F_N*LPL)/256, 256>>>(ro_w1, ro_b1, ro_w2, ro_b2, ro_w3, ro_b3,
                                      l2f, link_cap, flow_pdelay, out);
}